// round 12
// baseline (speedup 1.0000x reference)
#include <cuda_runtime.h>
#include <cstdint>
#include <climits>

#define BB   8
#define NN   4096
#define CIN  64
#define CMLP 128
#define COUT 256
#define SS   1024
#define NSAMP 32

// ---------------- device scratch (no allocations allowed) ----------------
__device__ float d_g[BB * NN * COUT];        // per-point post-MLP features (33.5 MB)
__device__ float d_Wcomb[CIN * COUT];        // W1 @ Wc
__device__ float d_bcomb[COUT];              // b1 @ Wc + bc
__device__ int   d_fpsidx[BB * SS];          // -1 sentinel, filled progressively by FPS
__device__ int   d_gidx[BB * SS * NSAMP];
__device__ int   d_counts[BB * NN];
__device__ float d_sum[COUT];
__device__ float d_sumsq[COUT];

// ---------------- packed fp32x2 helpers (bitwise-exact per-lane rn) ----------------
__device__ __forceinline__ unsigned long long f2_sub(unsigned long long a, unsigned long long b) {
    unsigned long long r; asm("sub.rn.f32x2 %0,%1,%2;" : "=l"(r) : "l"(a), "l"(b)); return r;
}
__device__ __forceinline__ unsigned long long f2_add(unsigned long long a, unsigned long long b) {
    unsigned long long r; asm("add.rn.f32x2 %0,%1,%2;" : "=l"(r) : "l"(a), "l"(b)); return r;
}
__device__ __forceinline__ unsigned long long f2_mul(unsigned long long a, unsigned long long b) {
    unsigned long long r; asm("mul.rn.f32x2 %0,%1,%2;" : "=l"(r) : "l"(a), "l"(b)); return r;
}
__device__ __forceinline__ unsigned long long f2_pack(float lo, float hi) {
    unsigned long long r; asm("mov.b64 %0,{%1,%2};" : "=l"(r) : "f"(lo), "f"(hi)); return r;
}
__device__ __forceinline__ void f2_unpack(float& lo, float& hi, unsigned long long v) {
    asm("mov.b64 {%0,%1},%2;" : "=f"(lo), "=f"(hi) : "l"(v));
}

// ---------------- K0: fold weights, init accumulators + sentinels ----------------
__global__ __launch_bounds__(256) void k0_prep(const float* __restrict__ W1,
                                               const float* __restrict__ b1,
                                               const float* __restrict__ Wc,
                                               const float* __restrict__ bc) {
    int blk = blockIdx.x, tid = threadIdx.x;
    if (blk < 64) {                       // Wcomb row blk
        const float* w1r = W1 + blk * CMLP;
        float acc = 0.f;
        for (int m = 0; m < CMLP; m++) acc += w1r[m] * Wc[m * COUT + tid];
        d_Wcomb[blk * COUT + tid] = acc;
    } else if (blk == 64) {               // bcomb
        float acc = bc[tid];
        for (int m = 0; m < CMLP; m++) acc += b1[m] * Wc[m * COUT + tid];
        d_bcomb[tid] = acc;
    } else if (blk < 193) {               // zero counts (128 blocks x 256)
        d_counts[(blk - 65) * 256 + tid] = 0;
    } else if (blk == 193) {              // zero stats
        d_sum[tid] = 0.f; d_sumsq[tid] = 0.f;
    } else {                              // fps sentinel (32 blocks x 256 = 8192)
        d_fpsidx[(blk - 194) * 256 + tid] = -1;
    }
}

// ---------------- K1: fused FPS (0..7) + GEMM (8..1031) + ball query (1032..1543) ----------------
__global__ __launch_bounds__(512) void k1_fused(const float* __restrict__ xyz,
                                                const float* __restrict__ points) {
    extern __shared__ float sm[];
    __shared__ unsigned long long s_keys[2][8];    // [parity][warp] tagged FPS keys
    __shared__ int sidx[16][NSAMP];
    int tid = threadIdx.x;

    if (blockIdx.x < BB) {
        // ===== exact FPS: 8 warps, 16 pts/thread, barrier-free tagged key exchange =====
        float* sx = sm; float* sy = sm + NN; float* sz = sm + 2 * NN;
        volatile unsigned long long* vk = &s_keys[0][0];   // [par*8 + w]
        int b = blockIdx.x;
        const float* xb = xyz + b * NN * 3;
        for (int i = tid; i < NN; i += 512) {
            sx[i] = xb[3 * i]; sy[i] = xb[3 * i + 1]; sz[i] = xb[3 * i + 2];
        }
        if (tid < 16) s_keys[tid >> 3][tid & 7] = ~0ull;   // tag=0xFFFFF != any step
        __syncthreads();                         // xyz + key init staged
        if (tid >= 256) return;                  // warps 8..15 retire; 8 warps continue

        // thread t owns points t, t+256, ..., t+3840 (ascending j -> ascending idx)
        unsigned long long p2x[8], p2y[8], p2z[8];
        float dmin[16];
        #pragma unroll
        for (int k = 0; k < 8; k++) {
            int i0 = tid + ((2 * k) << 8), i1 = tid + ((2 * k + 1) << 8);
            p2x[k] = f2_pack(sx[i0], sx[i1]);
            p2y[k] = f2_pack(sy[i0], sy[i1]);
            p2z[k] = f2_pack(sz[i0], sz[i1]);
        }
        #pragma unroll
        for (int j = 0; j < 16; j++) dmin[j] = 1e10f;

        int far = 0;
        int lane = tid & 31, warp = tid >> 5;
        volatile int* fout = d_fpsidx + b * SS;

        for (int step = 0; step < SS; step++) {
            if (tid == 0) fout[step] = far;      // progressive publish (payload word)
            float cx = sx[far], cy = sy[far], cz = sz[far];
            unsigned long long c2x = f2_pack(cx, cx);
            unsigned long long c2y = f2_pack(cy, cy);
            unsigned long long c2z = f2_pack(cz, cz);

            float best = -1.0f;
            #pragma unroll
            for (int k = 0; k < 8; k++) {
                unsigned long long dx = f2_sub(p2x[k], c2x);
                unsigned long long dy = f2_sub(p2y[k], c2y);
                unsigned long long dz = f2_sub(p2z[k], c2z);
                unsigned long long d2 = f2_add(f2_add(f2_mul(dx, dx), f2_mul(dy, dy)),
                                               f2_mul(dz, dz));
                float d0, d1; f2_unpack(d0, d1, d2);
                float m0 = fminf(dmin[2 * k],     d0); dmin[2 * k]     = m0;
                float m1 = fminf(dmin[2 * k + 1], d1); dmin[2 * k + 1] = m1;
                best = fmaxf(best, m0);
                best = fmaxf(best, m1);
            }

            unsigned fb = __float_as_uint(best);       // nonneg: uint order == float order
            unsigned wm = __reduce_max_sync(0xffffffffu, fb);
            int cand = 0x7fffffff;
            if (fb == wm) {
                int bj = 0;                            // first j == lowest in-thread index
                #pragma unroll
                for (int j = 15; j >= 0; j--) if (dmin[j] == best) bj = j;
                cand = tid + (bj << 8);
            }
            int wi = __reduce_min_sync(0xffffffffu, cand);   // lowest idx among warp maxima

            // post tagged key: [value:32 | step:20 | (4095-idx):12]; max-fold == value,
            // then lowest index. 2-slot parity ring; stale slot holds step-2 (tag mismatch).
            int par = step & 1;
            unsigned lo = ((unsigned)step << 12) | (unsigned)(4095 - wi);
            if (lane == 0)
                vk[par * 8 + warp] = ((unsigned long long)wm << 32) | lo;

            // barrier-free: spin until all 8 keys carry this step's tag, fold in regs
            unsigned long long kmax;
            for (;;) {
                bool ok = true;
                kmax = 0ull;
                #pragma unroll
                for (int w = 0; w < 8; w++) {
                    unsigned long long kv = vk[par * 8 + w];
                    ok &= (((unsigned)kv >> 12) == (unsigned)step);
                    kmax = kv > kmax ? kv : kmax;
                }
                if (ok) break;
            }
            far = 4095 - (int)((unsigned)kmax & 0xFFFu);
        }
    } else if (blockIdx.x < BB + 1024) {
        // ============ GEMM: g = points @ Wcomb + bcomb (32 rows per block) ============
        float* sW = sm;                // 32 x 256 (phase-tiled over k)
        float* sP = sm + 32 * 256;     // 32 x 64
        int blk  = blockIdx.x - BB;
        int row0 = blk * 32;
        const float* pb = points + (size_t)row0 * CIN;
        for (int i = tid; i < 32 * CIN; i += 512) sP[i] = pb[i];

        int o    = tid & 255;
        int half = tid >> 8;           // 0/1: rows [0,16) or [16,32)
        float acc[16];
        float bo = d_bcomb[o];
        #pragma unroll
        for (int r = 0; r < 16; r++) acc[r] = bo;

        const float4* sP4 = (const float4*)sP;
        #pragma unroll
        for (int phase = 0; phase < 2; phase++) {
            if (phase) __syncthreads();
            for (int i = tid; i < 32 * 256; i += 512) sW[i] = d_Wcomb[phase * 8192 + i];
            __syncthreads();
            #pragma unroll
            for (int k4 = 0; k4 < 8; k4++) {
                float w0 = sW[(k4 * 4 + 0) * 256 + o];
                float w1 = sW[(k4 * 4 + 1) * 256 + o];
                float w2 = sW[(k4 * 4 + 2) * 256 + o];
                float w3 = sW[(k4 * 4 + 3) * 256 + o];
                #pragma unroll
                for (int r = 0; r < 16; r++) {
                    float4 p = sP4[(half * 16 + r) * 16 + phase * 8 + k4];
                    acc[r] = acc[r] + p.x * w0 + p.y * w1 + p.z * w2 + p.w * w3;
                }
            }
        }
        float* go = d_g + (size_t)row0 * COUT;
        #pragma unroll
        for (int r = 0; r < 16; r++) go[(half * 16 + r) * 256 + o] = acc[r];
    } else {
        // ============ ball query: 16 warps = 16 centroids per block, spin on fpsidx ============
        float* sx = sm; float* sy = sm + NN; float* sz = sm + 2 * NN;
        int idx = blockIdx.x - (BB + 1024);   // [0, 512)
        int b   = idx >> 6;                   // 64 blocks per batch
        int grp = (idx & 63) * 16;
        const float* xb = xyz + b * NN * 3;
        for (int i = tid; i < NN; i += 512) {
            sx[i] = xb[3 * i]; sy[i] = xb[3 * i + 1]; sz[i] = xb[3 * i + 2];
        }
        __syncthreads();

        int warp = tid >> 5, lane = tid & 31;
        int s = grp + warp;
        // spin until FPS publishes this centroid (payload word, no fence needed)
        volatile int* fp = d_fpsidx + b * SS + s;
        int fidx = *fp;
        while (fidx < 0) { __nanosleep(200); fidx = *fp; }

        float cx = sx[fidx], cy = sy[fidx], cz = sz[fidx];
        const float R2 = (float)(0.15 * 0.15);

        int K = 0;
        for (int c = 0; c < NN; c += 32) {
            int n = c + lane;
            float dx = __fsub_rn(sx[n], cx);
            float dy = __fsub_rn(sy[n], cy);
            float dz = __fsub_rn(sz[n], cz);
            float d  = __fadd_rn(__fadd_rn(__fmul_rn(dx, dx), __fmul_rn(dy, dy)),
                                 __fmul_rn(dz, dz));
            bool in = !(d > R2);                               // matches `sqr > r2` exclusion
            unsigned mask = __ballot_sync(0xffffffffu, in);
            int pos = K + __popc(mask & ((1u << lane) - 1u));
            if (in && pos < NSAMP) sidx[warp][pos] = n;
            K += __popc(mask);
            if (K >= NSAMP) break;                             // warp-uniform
        }
        __syncwarp();
        int Kc = K < NSAMP ? K : NSAMP;                        // centroid always in-radius -> K>=1
        int first = sidx[warp][0];
        if (lane >= Kc) sidx[warp][lane] = first;              // pad with first index
        __syncwarp();
        int gi = sidx[warp][lane];
        d_gidx[(b * SS + s) * NSAMP + lane] = gi;
        atomicAdd(&d_counts[b * NN + gi], 1);                  // duplicates counted (matches gather)
    }
}

// ---------------- K3: count-weighted per-channel sums (2048 blocks x 16 rows) ----------------
__global__ __launch_bounds__(256) void k3_stats() {
    int o  = threadIdx.x;
    int r0 = blockIdx.x * 16;
    float s = 0.f, q = 0.f;
    #pragma unroll 4
    for (int r = 0; r < 16; r++) {
        int row = r0 + r;
        int c = d_counts[row];
        if (c) {
            float fc = (float)c;
            float v  = d_g[(size_t)row * COUT + o];
            s += fc * v;
            q += fc * v * v;
        }
    }
    atomicAdd(&d_sum[o], s);
    atomicAdd(&d_sumsq[o], q);
}

// ---------------- K5: BN finalize + gather + affine + relu + max (float2, 2 centroids/blk) ----------------
__global__ __launch_bounds__(256) void k5_out(const float* __restrict__ gamma,
                                              const float* __restrict__ beta,
                                              float* __restrict__ out) {
    __shared__ int si[2][NSAMP];
    int tid = threadIdx.x;
    int grpv = tid >> 7;                   // 0/1: which centroid
    int t    = tid & 127;                  // channel-pair id
    int bs   = blockIdx.x * 2 + grpv;      // b*1024 + s
    if (t < NSAMP) si[grpv][t] = d_gidx[bs * NSAMP + t];
    __syncthreads();

    // fold BN finalize (identical arithmetic in every block -> deterministic)
    const float invn = 1.0f / (float)(BB * SS * NSAMP);    // 1/262144
    float2 sum2 = *(const float2*)(d_sum   + 2 * t);
    float2 sq2  = *(const float2*)(d_sumsq + 2 * t);
    float2 ga2  = *(const float2*)(gamma   + 2 * t);
    float2 be2  = *(const float2*)(beta    + 2 * t);
    float mean0 = sum2.x * invn, mean1 = sum2.y * invn;
    float var0  = sq2.x * invn - mean0 * mean0;
    float var1  = sq2.y * invn - mean1 * mean1;
    float sc0   = ga2.x / sqrtf(var0 + 1e-5f);
    float sc1   = ga2.y / sqrtf(var1 + 1e-5f);
    float sh0   = be2.x - mean0 * sc0;
    float sh1   = be2.y - mean1 * sc1;

    int b = bs >> 10;
    const float* gb = d_g + (size_t)b * NN * COUT + 2 * t;
    float m0 = -3.4e38f, m1 = -3.4e38f;
    #pragma unroll
    for (int j = 0; j < NSAMP; j++) {
        float2 v = *(const float2*)(gb + (size_t)si[grpv][j] * COUT);
        m0 = fmaxf(m0, v.x * sc0 + sh0);
        m1 = fmaxf(m1, v.y * sc1 + sh1);
    }
    float2 r; r.x = fmaxf(m0, 0.0f); r.y = fmaxf(m1, 0.0f);   // relu commutes with max
    *(float2*)(out + (size_t)bs * COUT + 2 * t) = r;
}

// ---------------- launcher ----------------
extern "C" void kernel_launch(void* const* d_in, const int* in_sizes, int n_in,
                              void* d_out, int out_size) {
    const float* xyz    = (const float*)d_in[0];   // (8,4096,3)
    // d_in[1] = t (unused by reference)
    const float* points = (const float*)d_in[2];   // (8,4096,64)
    const float* W1     = (const float*)d_in[3];   // (64,128)
    const float* b1     = (const float*)d_in[4];   // (128)
    const float* Wc     = (const float*)d_in[5];   // (128,256)
    const float* bc     = (const float*)d_in[6];   // (256)
    const float* gamma  = (const float*)d_in[7];   // (256)
    const float* beta   = (const float*)d_in[8];   // (256)
    float* out = (float*)d_out;                    // (8,1024,256)

    const int SMEM_XYZ = 3 * NN * sizeof(float);   // 49152 bytes dynamic

    // One-time opt-in (runs on the correctness call, before graph capture).
    static const bool attrs_ok = [](){
        cudaFuncSetAttribute(k1_fused,
                             cudaFuncAttributeMaxDynamicSharedMemorySize, 56 * 1024);
        return true;
    }();
    (void)attrs_ok;

    k0_prep<<<226, 256>>>(W1, b1, Wc, bc);
    k1_fused<<<BB + 1024 + 512, 512, SMEM_XYZ>>>(xyz, points);
    k3_stats<<<2048, 256>>>();
    k5_out<<<BB * SS / 2, 256>>>(gamma, beta, out);
}